// round 16
// baseline (speedup 1.0000x reference)
#include <cuda_runtime.h>
#include <cuda_fp16.h>
#include <math.h>
#include <stdint.h>

// Problem constants
#define BATCH   4
#define SEQ     1024
#define DMODEL  1024
#define DFF_    4096
#define NHEAD   16
#define DHEAD   64
#define ROWS    (BATCH * SEQ)
#define LN_EPS  1e-5f
#define SCALE_L2E (0.03125f * 1.4426950408889634f)
#define ONES_H2 0x3C003C00u

// ---------------------------------------------------------------------------
// Scratch buffers
// ---------------------------------------------------------------------------
__device__ float  g_o  [ROWS * DMODEL];
__device__ float  g_x  [ROWS * DMODEL];
__device__ float  g_y  [ROWS * DMODEL];

__device__ __half h_qi [ROWS * DMODEL];
__device__ __half h_ki [ROWS * DMODEL];
__device__ __half h_q  [ROWS * DMODEL];
__device__ __half h_k  [ROWS * DMODEL];
__device__ __half h_v  [ROWS * DMODEL];
__device__ __half h_vt [ROWS * DMODEL];
__device__ __half h_att[ROWS * DMODEL];
__device__ __half h_x  [ROWS * DMODEL];
__device__ __half h_ff [ROWS * DFF_ ];
__device__ __half h_w  [12 * 1024 * 1024];

// ---------------------------------------------------------------------------
// PTX helpers
// ---------------------------------------------------------------------------
__device__ __forceinline__ void cp_async16(uint32_t s, const void* g) {
    asm volatile("cp.async.cg.shared.global [%0], [%1], 16;\n" :: "r"(s), "l"(g));
}
__device__ __forceinline__ void mma_f16(float* c, uint32_t a0, uint32_t a1,
                                        uint32_t a2, uint32_t a3,
                                        uint32_t b0, uint32_t b1) {
    asm volatile(
        "mma.sync.aligned.m16n8k16.row.col.f32.f16.f16.f32 "
        "{%0,%1,%2,%3}, {%4,%5,%6,%7}, {%8,%9}, {%0,%1,%2,%3};\n"
        : "+f"(c[0]), "+f"(c[1]), "+f"(c[2]), "+f"(c[3])
        : "r"(a0), "r"(a1), "r"(a2), "r"(a3), "r"(b0), "r"(b1));
}
__device__ __forceinline__ void ldm_x4(uint32_t& r0, uint32_t& r1,
                                       uint32_t& r2, uint32_t& r3, uint32_t a) {
    asm volatile("ldmatrix.sync.aligned.m8n8.x4.shared.b16 {%0,%1,%2,%3}, [%4];"
                 : "=r"(r0), "=r"(r1), "=r"(r2), "=r"(r3) : "r"(a));
}
// exp2 of two f32 deltas, computed in f16x2 (result = P fragment half)
__device__ __forceinline__ uint32_t exp2_h2(float x, float y) {
    __half2 h = __floats2half2_rn(x, y);
    uint32_t u = *reinterpret_cast<uint32_t*>(&h);
    asm("ex2.approx.f16x2 %0, %0;" : "+r"(u));
    return u;
}

// ---------------------------------------------------------------------------
// Pre-passes. conv_w vectorized: 1 float4 load + 1 uint2 (4-half) store/thread.
// ---------------------------------------------------------------------------
__global__ void __launch_bounds__(256)
conv_w(const float* __restrict__ src, __half* __restrict__ dst, int K, int N)
{
    __shared__ float t[32][33];
    const int n0 = blockIdx.x * 32, k0 = blockIdx.y * 32;
    const int tid = threadIdx.x;
    {
        const int row = tid >> 3;       // k-row 0..31
        const int c4  = tid & 7;        // float4 chunk 0..7
        float4 v = *reinterpret_cast<const float4*>(
            src + (size_t)(k0 + row) * N + n0 + c4 * 4);
        t[row][c4 * 4 + 0] = v.x; t[row][c4 * 4 + 1] = v.y;
        t[row][c4 * 4 + 2] = v.z; t[row][c4 * 4 + 3] = v.w;
    }
    __syncthreads();
    {
        const int n  = tid >> 3;        // n-row 0..31
        const int kc = tid & 7;         // 4-k chunk 0..7
        __half2 h0 = __floats2half2_rn(t[kc * 4 + 0][n], t[kc * 4 + 1][n]);
        __half2 h1 = __floats2half2_rn(t[kc * 4 + 2][n], t[kc * 4 + 3][n]);
        uint2 u;
        u.x = *reinterpret_cast<uint32_t*>(&h0);
        u.y = *reinterpret_cast<uint32_t*>(&h1);
        *reinterpret_cast<uint2*>(dst + (size_t)(n0 + n) * K + k0 + kc * 4) = u;
    }
}

__global__ void __launch_bounds__(256)
conv_a(const float* __restrict__ src, __half* __restrict__ dst)
{
    const size_t i = ((size_t)blockIdx.x * 256 + threadIdx.x) * 4;
    float4 v = *reinterpret_cast<const float4*>(src + i);
    *reinterpret_cast<__half2*>(dst + i)     = __floats2half2_rn(v.x, v.y);
    *reinterpret_cast<__half2*>(dst + i + 2) = __floats2half2_rn(v.z, v.w);
}

__global__ void __launch_bounds__(256)
vtrans(const __half* __restrict__ src, __half* __restrict__ dst)
{
    __shared__ __half t[32][33];
    const int z = blockIdx.z;
    const __half* s = src + (size_t)z * SEQ * DMODEL;
    __half*       d = dst + (size_t)z * DMODEL * SEQ;
    const int c0 = blockIdx.x * 32, r0 = blockIdx.y * 32;
    const int x = threadIdx.x & 31, y = threadIdx.x >> 5;
    #pragma unroll
    for (int j = 0; j < 4; j++)
        t[y + j * 8][x] = s[(size_t)(r0 + y + j * 8) * DMODEL + c0 + x];
    __syncthreads();
    #pragma unroll
    for (int j = 0; j < 4; j++)
        d[(size_t)(c0 + y + j * 8) * SEQ + r0 + x] = t[x][y + j * 8];
}

// ---------------------------------------------------------------------------
// fp16 GEMM (R7-proven): C[M,N] = Ah[M,K] @ Bh[N,K]^T + bias.
// 128x128 tile, BK=32, 256 threads, ldmatrix, 3-stage cp.async.
// ---------------------------------------------------------------------------
struct GemmBatch {
    const __half* A[3];
    const __half* B[3];
    const float*  bias[3];
    float*        C[3];
    __half*       Ch[3];
};

#define HBK 32
#define ROWB 80
#define STAGE_BYTES (128 * ROWB)
#define GEMM_SMEM (6 * STAGE_BYTES)     // 61440

template<int RELU, int OUTH>
__global__ void __launch_bounds__(256, 2)
gemm_f16(GemmBatch gb, int M, int N, int K)
{
    extern __shared__ __align__(128) char smem[];

    const int z = blockIdx.z;
    const __half* __restrict__ A    = gb.A[z];
    const __half* __restrict__ Bt   = gb.B[z];
    const float*  __restrict__ bias = gb.bias[z];
    float*        __restrict__ C    = gb.C[z];
    __half*       __restrict__ Ch   = gb.Ch[z];

    const int tid  = threadIdx.x;
    const int lane = tid & 31;
    const int warp = tid >> 5;
    const int wm   = (warp >> 2) * 64;
    const int wn   = (warp & 3) * 32;
    const int crow = blockIdx.y * 128;
    const int ccol = blockIdx.x * 128;

    const __half* Ap = A  + (size_t)crow * K;
    const __half* Bp = Bt + (size_t)ccol * K;

    const uint32_t smem_base = (uint32_t)__cvta_generic_to_shared(smem);

    const int l_row = tid >> 2;
    const int l_c16 = tid & 3;

    const uint32_t arow_off = (uint32_t)((lane & 7) * ROWB
                            + ((lane >> 3) & 1) * 8 * ROWB + (lane >> 4) * 16);
    const uint32_t brow_off = (uint32_t)((lane & 7) * ROWB
                            + ((lane >> 3) & 1) * 16 + (lane >> 4) * 8 * ROWB);

    auto load_stage = [&](int st, int k0) {
        const uint32_t as = smem_base + st * STAGE_BYTES;
        const uint32_t bs = smem_base + (3 + st) * STAGE_BYTES;
        #pragma unroll
        for (int i = 0; i < 2; i++) {
            const int row = l_row + i * 64;
            const uint32_t so = (uint32_t)(row * ROWB + l_c16 * 16);
            const size_t go = (size_t)row * K + k0 + l_c16 * 8;
            cp_async16(as + so, Ap + go);
            cp_async16(bs + so, Bp + go);
        }
        asm volatile("cp.async.commit_group;\n" ::: "memory");
    };

    float acc[4][4][4];
    #pragma unroll
    for (int mi = 0; mi < 4; mi++)
        #pragma unroll
        for (int ni = 0; ni < 4; ni++)
            #pragma unroll
            for (int r = 0; r < 4; r++) acc[mi][ni][r] = 0.f;

    const int fr = lane >> 2;
    const int fc = lane & 3;

    const int NIT = K / HBK;
    load_stage(0, 0);
    load_stage(1, HBK);

    for (int it = 0; it < NIT; it++) {
        const int cur = it % 3;
        if (it + 1 < NIT) {
            asm volatile("cp.async.wait_group 1;\n" ::: "memory");
        } else {
            asm volatile("cp.async.wait_group 0;\n" ::: "memory");
        }
        __syncthreads();
        if (it + 2 < NIT) load_stage((it + 2) % 3, (it + 2) * HBK);

        const uint32_t as = smem_base + cur * STAGE_BYTES;
        const uint32_t bs = smem_base + (3 + cur) * STAGE_BYTES;

        #pragma unroll
        for (int ks = 0; ks < 2; ks++) {
            const int kb = ks * 32;
            uint32_t af[4][4];
            uint32_t bf[4][2];
            #pragma unroll
            for (int mi = 0; mi < 4; mi++)
                ldm_x4(af[mi][0], af[mi][1], af[mi][2], af[mi][3],
                       as + (wm + mi * 16) * ROWB + kb + arow_off);
            #pragma unroll
            for (int n2 = 0; n2 < 2; n2++)
                ldm_x4(bf[2 * n2][0], bf[2 * n2][1], bf[2 * n2 + 1][0], bf[2 * n2 + 1][1],
                       bs + (wn + n2 * 16) * ROWB + kb + brow_off);
            #pragma unroll
            for (int mi = 0; mi < 4; mi++)
                #pragma unroll
                for (int ni = 0; ni < 4; ni++)
                    mma_f16(acc[mi][ni], af[mi][0], af[mi][1], af[mi][2], af[mi][3],
                            bf[ni][0], bf[ni][1]);
        }
        __syncthreads();
    }

    #pragma unroll
    for (int mi = 0; mi < 4; mi++) {
        #pragma unroll
        for (int ni = 0; ni < 4; ni++) {
            const int row = crow + wm + mi * 16 + fr;
            const int col = ccol + wn + ni * 8 + 2 * fc;
            const float b0 = bias[col], b1 = bias[col + 1];
            float2 v0 = make_float2(acc[mi][ni][0] + b0, acc[mi][ni][1] + b1);
            float2 v1 = make_float2(acc[mi][ni][2] + b0, acc[mi][ni][3] + b1);
            if (RELU) {
                v0.x = fmaxf(v0.x, 0.f); v0.y = fmaxf(v0.y, 0.f);
                v1.x = fmaxf(v1.x, 0.f); v1.y = fmaxf(v1.y, 0.f);
            }
            if (OUTH) {
                *reinterpret_cast<__half2*>(Ch + (size_t)row * N + col) =
                    __floats2half2_rn(v0.x, v0.y);
                *reinterpret_cast<__half2*>(Ch + (size_t)(row + 8) * N + col) =
                    __floats2half2_rn(v1.x, v1.y);
            } else {
                *reinterpret_cast<float2*>(C + (size_t)row * N + col)       = v0;
                *reinterpret_cast<float2*>(C + (size_t)(row + 8) * N + col) = v1;
            }
        }
    }
}

// ---------------------------------------------------------------------------
// f16 flash attention (R13-proven). 256 threads, q tile 128, kv tile 64.
// R7 pipeline; softmax: f16x2 exp2 (ex2.approx.f16x2) + ones-mma row sums.
// ---------------------------------------------------------------------------
#define FPB 144
#define FKV_B (64 * FPB)
#define FQ_B  (128 * FPB)
#define FLASH_SMEM (FQ_B + 4 * FKV_B)

__global__ void __launch_bounds__(256)
flash_f16(const __half* __restrict__ Qp, const __half* __restrict__ Kp,
          const __half* __restrict__ Vt, __half* __restrict__ O)
{
    extern __shared__ __align__(128) char fsm[];
    const uint32_t qsb = (uint32_t)__cvta_generic_to_shared(fsm);
    const uint32_t ksb = qsb + FQ_B;
    const uint32_t vsb = qsb + FQ_B + 2 * FKV_B;

    const int tid  = threadIdx.x;
    const int lane = tid & 31;
    const int w    = tid >> 5;
    const int fr   = lane >> 2;
    const int fc   = lane & 3;

    const int qt = blockIdx.x;
    const int b  = blockIdx.y >> 4;
    const int h  = blockIdx.y & 15;

    const size_t qoff = ((size_t)b * SEQ + qt * 128) * DMODEL + h * DHEAD;
    const size_t koff = (size_t)b * SEQ * DMODEL + h * DHEAD;
    const size_t voff = ((size_t)b * DMODEL + h * DHEAD) * SEQ;

    const uint32_t arow_off = (uint32_t)((lane & 7) * FPB
                            + ((lane >> 3) & 1) * 8 * FPB + (lane >> 4) * 16);
    const uint32_t brow_off = (uint32_t)((lane & 7) * FPB
                            + ((lane >> 3) & 1) * 16 + (lane >> 4) * 8 * FPB);

    #pragma unroll
    for (int j = 0; j < 4; j++) {
        const int idx = tid + j * 256;
        const int row = idx >> 3, ch = idx & 7;
        cp_async16(qsb + row * FPB + ch * 16, Qp + qoff + (size_t)row * DMODEL + ch * 8);
    }
    auto stage_kv = [&](int buf, int kt) {
        #pragma unroll
        for (int j = 0; j < 2; j++) {
            const int idx = tid + j * 256;
            const int row = idx >> 3, ch = idx & 7;
            cp_async16(ksb + buf * FKV_B + row * FPB + ch * 16,
                       Kp + koff + (size_t)(kt * 64 + row) * DMODEL + ch * 8);
            cp_async16(vsb + buf * FKV_B + row * FPB + ch * 16,
                       Vt + voff + (size_t)row * SEQ + kt * 64 + ch * 8);
        }
        asm volatile("cp.async.commit_group;\n" ::: "memory");
    };
    stage_kv(0, 0);   // commits q copies too

    float m0 = -1e30f, m1 = -1e30f;
    float oacc[8][4];
    float lacc[4];    // persistent row-sum accumulator (ones-mma output)
    #pragma unroll
    for (int ni = 0; ni < 8; ni++)
        #pragma unroll
        for (int r = 0; r < 4; r++) oacc[ni][r] = 0.f;
    #pragma unroll
    for (int r = 0; r < 4; r++) lacc[r] = 0.f;

    const int qrow = w * 16;
    const int NT = SEQ / 64;

    for (int kt = 0; kt < NT; kt++) {
        const int cur = kt & 1;
        if (kt + 1 < NT) {
            stage_kv(cur ^ 1, kt + 1);
            asm volatile("cp.async.wait_group 1;\n" ::: "memory");
        } else {
            asm volatile("cp.async.wait_group 0;\n" ::: "memory");
        }
        __syncthreads();

        const uint32_t kb_s = ksb + cur * FKV_B;
        const uint32_t vb_s = vsb + cur * FKV_B;

        // ---- S = Q K^T ----
        float sacc[8][4];
        #pragma unroll
        for (int ni = 0; ni < 8; ni++)
            #pragma unroll
            for (int r = 0; r < 4; r++) sacc[ni][r] = 0.f;

        #pragma unroll
        for (int kg = 0; kg < 4; kg++) {
            const int kb = kg * 32;
            uint32_t a0, a1, a2, a3;
            ldm_x4(a0, a1, a2, a3, qsb + qrow * FPB + kb + arow_off);
            uint32_t bf[8][2];
            #pragma unroll
            for (int n2 = 0; n2 < 4; n2++)
                ldm_x4(bf[2 * n2][0], bf[2 * n2][1], bf[2 * n2 + 1][0], bf[2 * n2 + 1][1],
                       kb_s + (n2 * 16) * FPB + kb + brow_off);
            #pragma unroll
            for (int ni = 0; ni < 8; ni++)
                mma_f16(sacc[ni], a0, a1, a2, a3, bf[ni][0], bf[ni][1]);
        }

        // ---- online softmax: max, corr, f16x2 exp2 ----
        float mx0 = -1e30f, mx1 = -1e30f;
        #pragma unroll
        for (int ni = 0; ni < 8; ni++) {
            sacc[ni][0] *= SCALE_L2E; sacc[ni][1] *= SCALE_L2E;
            sacc[ni][2] *= SCALE_L2E; sacc[ni][3] *= SCALE_L2E;
            mx0 = fmaxf(mx0, fmaxf(sacc[ni][0], sacc[ni][1]));
            mx1 = fmaxf(mx1, fmaxf(sacc[ni][2], sacc[ni][3]));
        }
        mx0 = fmaxf(mx0, __shfl_xor_sync(0xffffffffu, mx0, 1));
        mx0 = fmaxf(mx0, __shfl_xor_sync(0xffffffffu, mx0, 2));
        mx1 = fmaxf(mx1, __shfl_xor_sync(0xffffffffu, mx1, 1));
        mx1 = fmaxf(mx1, __shfl_xor_sync(0xffffffffu, mx1, 2));

        const float mn0 = fmaxf(m0, mx0), mn1 = fmaxf(m1, mx1);
        const float corr0 = exp2f(m0 - mn0), corr1 = exp2f(m1 - mn1);
        m0 = mn0; m1 = mn1;

        // P fragments directly via f16x2 exp2
        uint32_t pf[8][2];
        #pragma unroll
        for (int ni = 0; ni < 8; ni++) {
            pf[ni][0] = exp2_h2(sacc[ni][0] - mn0, sacc[ni][1] - mn0);
            pf[ni][1] = exp2_h2(sacc[ni][2] - mn1, sacc[ni][3] - mn1);
        }

        // rescale running accumulators
        #pragma unroll
        for (int ni = 0; ni < 8; ni++) {
            oacc[ni][0] *= corr0; oacc[ni][1] *= corr0;
            oacc[ni][2] *= corr1; oacc[ni][3] *= corr1;
        }
        lacc[0] *= corr0; lacc[1] *= corr0;
        lacc[2] *= corr1; lacc[3] *= corr1;

        // ---- O += P V  and  l += P @ ones ----
        #pragma unroll
        for (int kg = 0; kg < 4; kg++) {
            const int kb = kg * 32;
            const uint32_t a0 = pf[2 * kg][0];
            const uint32_t a1 = pf[2 * kg][1];
            const uint32_t a2 = pf[2 * kg + 1][0];
            const uint32_t a3 = pf[2 * kg + 1][1];
            uint32_t bf[8][2];
            #pragma unroll
            for (int n2 = 0; n2 < 4; n2++)
                ldm_x4(bf[2 * n2][0], bf[2 * n2][1], bf[2 * n2 + 1][0], bf[2 * n2 + 1][1],
                       vb_s + (n2 * 16) * FPB + kb + brow_off);
            #pragma unroll
            for (int ni = 0; ni < 8; ni++)
                mma_f16(oacc[ni], a0, a1, a2, a3, bf[ni][0], bf[ni][1]);
            mma_f16(lacc, a0, a1, a2, a3, ONES_H2, ONES_H2);   // row sums
        }
        __syncthreads();   // all reads of cur done before refill next iter
    }

    const float inv0 = 1.f / lacc[0];
    const float inv1 = 1.f / lacc[2];
    const size_t row0 = (size_t)b * SEQ + qt * 128 + qrow + fr;
    const size_t row1 = row0 + 8;
    #pragma unroll
    for (int ni = 0; ni < 8; ni++) {
        const int col = h * DHEAD + ni * 8 + 2 * fc;
        *reinterpret_cast<__half2*>(O + row0 * DMODEL + col) =
            __floats2half2_rn(oacc[ni][0] * inv0, oacc[ni][1] * inv0);
        *reinterpret_cast<__half2*>(O + row1 * DMODEL + col) =
            __floats2half2_rn(oacc[ni][2] * inv1, oacc[ni][3] * inv1);
    }
}

// ---------------------------------------------------------------------------
// Fused residual add + LayerNorm (float4 vectorized)
// ---------------------------------------------------------------------------
template<int WH>
__global__ void __launch_bounds__(256)
add_ln(const float* __restrict__ A, const float* __restrict__ R,
       const float* __restrict__ g, const float* __restrict__ be,
       float* __restrict__ out, __half* __restrict__ outh)
{
    const int row = blockIdx.x;
    const int tid = threadIdx.x;
    const size_t base = (size_t)row * DMODEL;
    const int c = tid * 4;

    float4 a4 = *reinterpret_cast<const float4*>(A + base + c);
    float4 r4 = *reinterpret_cast<const float4*>(R + base + c);
    float x[4] = {a4.x + r4.x, a4.y + r4.y, a4.z + r4.z, a4.w + r4.w};
    float sum = x[0] + x[1] + x[2] + x[3];

    __shared__ float red[8];
    __shared__ float red2[8];
    #pragma unroll
    for (int off = 16; off; off >>= 1)
        sum += __shfl_xor_sync(0xffffffffu, sum, off);
    if ((tid & 31) == 0) red[tid >> 5] = sum;
    __syncthreads();
    float tot = 0.f;
    #pragma unroll
    for (int wq = 0; wq < 8; wq++) tot += red[wq];
    const float mean = tot * (1.f / (float)DMODEL);

    float vsum = 0.f;
    #pragma unroll
    for (int i = 0; i < 4; i++) {
        x[i] -= mean;
        vsum += x[i] * x[i];
    }
    #pragma unroll
    for (int off = 16; off; off >>= 1)
        vsum += __shfl_xor_sync(0xffffffffu, vsum, off);
    if ((tid & 31) == 0) red2[tid >> 5] = vsum;
    __syncthreads();
    float vtot = 0.f;
    #pragma unroll
    for (int wq = 0; wq < 8; wq++) vtot += red2[wq];
    const float rstd = rsqrtf(vtot * (1.f / (float)DMODEL) + LN_EPS);

    float4 g4  = *reinterpret_cast<const float4*>(g + c);
    float4 be4 = *reinterpret_cast<const float4*>(be + c);
    float4 v;
    v.x = x[0] * rstd * g4.x + be4.x;
    v.y = x[1] * rstd * g4.y + be4.y;
    v.z = x[2] * rstd * g4.z + be4.z;
    v.w = x[3] * rstd * g4.w + be4.w;
    *reinterpret_cast<float4*>(out + base + c) = v;
    if (WH) {
        *reinterpret_cast<__half2*>(outh + base + c)     = __floats2half2_rn(v.x, v.y);
        *reinterpret_cast<__half2*>(outh + base + c + 2) = __floats2half2_rn(v.z, v.w);
    }
}

// ---------------------------------------------------------------------------
// Launch
// ---------------------------------------------------------------------------
extern "C" void kernel_launch(void* const* d_in, const int* in_sizes, int n_in,
                              void* d_out, int out_size)
{
    (void)in_sizes; (void)n_in; (void)out_size;

    const float* Q   = (const float*)d_in[0];
    const float* Kin = (const float*)d_in[1];
    const float* Wq  = (const float*)d_in[2];
    const float* bq  = (const float*)d_in[3];
    const float* Wk  = (const float*)d_in[4];
    const float* bk  = (const float*)d_in[5];
    const float* Wv  = (const float*)d_in[6];
    const float* bv  = (const float*)d_in[7];
    const float* Wo  = (const float*)d_in[8];
    const float* bo  = (const float*)d_in[9];
    const float* W1  = (const float*)d_in[10];
    const float* b1  = (const float*)d_in[11];
    const float* W2  = (const float*)d_in[12];
    const float* b2  = (const float*)d_in[13];
    const float* g0  = (const float*)d_in[14];
    const float* be0 = (const float*)d_in[15];
    const float* g1  = (const float*)d_in[16];
    const float* be1 = (const float*)d_in[17];
    float* out = (float*)d_out;

    float  *po, *px, *py;
    __half *qih, *kih, *pqh, *pkh, *pvh, *pvt, *patth, *pxh, *pffh, *pw;
    cudaGetSymbolAddress((void**)&po,    g_o);
    cudaGetSymbolAddress((void**)&px,    g_x);
    cudaGetSymbolAddress((void**)&py,    g_y);
    cudaGetSymbolAddress((void**)&qih,   h_qi);
    cudaGetSymbolAddress((void**)&kih,   h_ki);
    cudaGetSymbolAddress((void**)&pqh,   h_q);
    cudaGetSymbolAddress((void**)&pkh,   h_k);
    cudaGetSymbolAddress((void**)&pvh,   h_v);
    cudaGetSymbolAddress((void**)&pvt,   h_vt);
    cudaGetSymbolAddress((void**)&patth, h_att);
    cudaGetSymbolAddress((void**)&pxh,   h_x);
    cudaGetSymbolAddress((void**)&pffh,  h_ff);
    cudaGetSymbolAddress((void**)&pw,    h_w);

    __half* wtq = pw;
    __half* wtk = pw + 1 * 1024 * 1024;
    __half* wtv = pw + 2 * 1024 * 1024;
    __half* wto = pw + 3 * 1024 * 1024;
    __half* wt1 = pw + 4 * 1024 * 1024;
    __half* wt2 = pw + 8 * 1024 * 1024;

    cudaFuncSetAttribute(gemm_f16<0, 0>, cudaFuncAttributeMaxDynamicSharedMemorySize, GEMM_SMEM);
    cudaFuncSetAttribute(gemm_f16<0, 1>, cudaFuncAttributeMaxDynamicSharedMemorySize, GEMM_SMEM);
    cudaFuncSetAttribute(gemm_f16<1, 1>, cudaFuncAttributeMaxDynamicSharedMemorySize, GEMM_SMEM);
    cudaFuncSetAttribute(flash_f16, cudaFuncAttributeMaxDynamicSharedMemorySize, FLASH_SMEM);

    // pre-passes (separate launches; conv_w vectorized)
    conv_w<<<dim3(32, 32),  256>>>(Wq, wtq, 1024, 1024);
    conv_w<<<dim3(32, 32),  256>>>(Wk, wtk, 1024, 1024);
    conv_w<<<dim3(32, 32),  256>>>(Wv, wtv, 1024, 1024);
    conv_w<<<dim3(32, 32),  256>>>(Wo, wto, 1024, 1024);
    conv_w<<<dim3(128, 32), 256>>>(W1, wt1, 1024, 4096);
    conv_w<<<dim3(32, 128), 256>>>(W2, wt2, 4096, 1024);
    conv_a<<<ROWS * DMODEL / 1024, 256>>>(Q,   qih);
    conv_a<<<ROWS * DMODEL / 1024, 256>>>(Kin, kih);

    // QKV projections (f16 out)
    {
        GemmBatch gb = {};
        gb.A[0] = qih; gb.B[0] = wtq; gb.bias[0] = bq; gb.Ch[0] = pqh;
        gb.A[1] = kih; gb.B[1] = wtk; gb.bias[1] = bk; gb.Ch[1] = pkh;
        gb.A[2] = kih; gb.B[2] = wtv; gb.bias[2] = bv; gb.Ch[2] = pvh;
        gemm_f16<0, 1><<<dim3(8, 32, 3), 256, GEMM_SMEM>>>(gb, ROWS, DMODEL, DMODEL);
    }

    vtrans<<<dim3(32, 32, 4), 256>>>(pvh, pvt);
    flash_f16<<<dim3(SEQ / 128, BATCH * NHEAD), 256, FLASH_SMEM>>>(pqh, pkh, pvt, patth);

    // O projection + residual + LN0
    {
        GemmBatch gb = {};
        gb.A[0] = patth; gb.B[0] = wto; gb.bias[0] = bo; gb.C[0] = po;
        gemm_f16<0, 0><<<dim3(8, 32, 1), 256, GEMM_SMEM>>>(gb, ROWS, DMODEL, DMODEL);
    }
    add_ln<1><<<ROWS, 256>>>(po, Q, g0, be0, px, pxh);

    // FFN
    {
        GemmBatch gb = {};
        gb.A[0] = pxh; gb.B[0] = wt1; gb.bias[0] = b1; gb.Ch[0] = pffh;
        gemm_f16<1, 1><<<dim3(32, 32, 1), 256, GEMM_SMEM>>>(gb, ROWS, DFF_, DMODEL);
    }
    {
        GemmBatch gb = {};
        gb.A[0] = pffh; gb.B[0] = wt2; gb.bias[0] = b2; gb.C[0] = py;
        gemm_f16<0, 0><<<dim3(8, 32, 1), 256, GEMM_SMEM>>>(gb, ROWS, DMODEL, DFF_);
    }
    add_ln<0><<<ROWS, 256>>>(py, px, g1, be1, out, nullptr);
}

// round 17
// speedup vs baseline: 1.0227x; 1.0227x over previous
#include <cuda_runtime.h>
#include <cuda_fp16.h>
#include <math.h>
#include <stdint.h>

// Problem constants
#define BATCH   4
#define SEQ     1024
#define DMODEL  1024
#define DFF_    4096
#define NHEAD   16
#define DHEAD   64
#define ROWS    (BATCH * SEQ)
#define LN_EPS  1e-5f
#define SCALE_L2E (0.03125f * 1.4426950408889634f)
#define ONES_H2 0x3C003C00u

// ---------------------------------------------------------------------------
// Scratch buffers
// ---------------------------------------------------------------------------
__device__ float  g_o  [ROWS * DMODEL];
__device__ float  g_x  [ROWS * DMODEL];
__device__ float  g_y  [ROWS * DMODEL];

__device__ __half h_qi [ROWS * DMODEL];
__device__ __half h_ki [ROWS * DMODEL];
__device__ __half h_q  [ROWS * DMODEL];
__device__ __half h_k  [ROWS * DMODEL];
__device__ __half h_vt [ROWS * DMODEL];    // V written TRANSPOSED by QKV epilogue
__device__ __half h_att[ROWS * DMODEL];
__device__ __half h_x  [ROWS * DMODEL];
__device__ __half h_ff [ROWS * DFF_ ];
__device__ __half h_w  [12 * 1024 * 1024];

// ---------------------------------------------------------------------------
// PTX helpers
// ---------------------------------------------------------------------------
__device__ __forceinline__ void cp_async16(uint32_t s, const void* g) {
    asm volatile("cp.async.cg.shared.global [%0], [%1], 16;\n" :: "r"(s), "l"(g));
}
__device__ __forceinline__ void mma_f16(float* c, uint32_t a0, uint32_t a1,
                                        uint32_t a2, uint32_t a3,
                                        uint32_t b0, uint32_t b1) {
    asm volatile(
        "mma.sync.aligned.m16n8k16.row.col.f32.f16.f16.f32 "
        "{%0,%1,%2,%3}, {%4,%5,%6,%7}, {%8,%9}, {%0,%1,%2,%3};\n"
        : "+f"(c[0]), "+f"(c[1]), "+f"(c[2]), "+f"(c[3])
        : "r"(a0), "r"(a1), "r"(a2), "r"(a3), "r"(b0), "r"(b1));
}
__device__ __forceinline__ void ldm_x4(uint32_t& r0, uint32_t& r1,
                                       uint32_t& r2, uint32_t& r3, uint32_t a) {
    asm volatile("ldmatrix.sync.aligned.m8n8.x4.shared.b16 {%0,%1,%2,%3}, [%4];"
                 : "=r"(r0), "=r"(r1), "=r"(r2), "=r"(r3) : "r"(a));
}
// exp2 of two f32 deltas, computed in f16x2 (result = P fragment half)
__device__ __forceinline__ uint32_t exp2_h2(float x, float y) {
    __half2 h = __floats2half2_rn(x, y);
    uint32_t u = *reinterpret_cast<uint32_t*>(&h);
    asm("ex2.approx.f16x2 %0, %0;" : "+r"(u));
    return u;
}

// ---------------------------------------------------------------------------
// Pre-passes (conv_w vectorized, R16)
// ---------------------------------------------------------------------------
__global__ void __launch_bounds__(256)
conv_w(const float* __restrict__ src, __half* __restrict__ dst, int K, int N)
{
    __shared__ float t[32][33];
    const int n0 = blockIdx.x * 32, k0 = blockIdx.y * 32;
    const int tid = threadIdx.x;
    {
        const int row = tid >> 3;
        const int c4  = tid & 7;
        float4 v = *reinterpret_cast<const float4*>(
            src + (size_t)(k0 + row) * N + n0 + c4 * 4);
        t[row][c4 * 4 + 0] = v.x; t[row][c4 * 4 + 1] = v.y;
        t[row][c4 * 4 + 2] = v.z; t[row][c4 * 4 + 3] = v.w;
    }
    __syncthreads();
    {
        const int n  = tid >> 3;
        const int kc = tid & 7;
        __half2 h0 = __floats2half2_rn(t[kc * 4 + 0][n], t[kc * 4 + 1][n]);
        __half2 h1 = __floats2half2_rn(t[kc * 4 + 2][n], t[kc * 4 + 3][n]);
        uint2 u;
        u.x = *reinterpret_cast<uint32_t*>(&h0);
        u.y = *reinterpret_cast<uint32_t*>(&h1);
        *reinterpret_cast<uint2*>(dst + (size_t)(n0 + n) * K + k0 + kc * 4) = u;
    }
}

__global__ void __launch_bounds__(256)
conv_a(const float* __restrict__ src, __half* __restrict__ dst)
{
    const size_t i = ((size_t)blockIdx.x * 256 + threadIdx.x) * 4;
    float4 v = *reinterpret_cast<const float4*>(src + i);
    *reinterpret_cast<__half2*>(dst + i)     = __floats2half2_rn(v.x, v.y);
    *reinterpret_cast<__half2*>(dst + i + 2) = __floats2half2_rn(v.z, v.w);
}

// ---------------------------------------------------------------------------
// fp16 GEMM (R7-proven mainloop): C[M,N] = Ah[M,K] @ Bh[N,K]^T + bias.
// 128x128 tile, BK=32, 256 threads, ldmatrix, 3-stage cp.async.
// OUTH=1 + z==trv_z: epilogue stages the f16 tile TRANSPOSED in smem (the
// pipeline buffers are dead after the mainloop) and writes it coalesced
// along the token axis into vt[(b*DMODEL + col)*SEQ + tok].
// ---------------------------------------------------------------------------
struct GemmBatch {
    const __half* A[3];
    const __half* B[3];
    const float*  bias[3];
    float*        C[3];
    __half*       Ch[3];
    int           trv_z;    // instance to transpose-store (-1: none)
};

#define HBK 32
#define ROWB 80
#define STAGE_BYTES (128 * ROWB)
#define GEMM_SMEM (6 * STAGE_BYTES)     // 61440
#define TPH 136                          // transpose smem pitch in halfs

template<int RELU, int OUTH>
__global__ void __launch_bounds__(256, 2)
gemm_f16(GemmBatch gb, int M, int N, int K)
{
    extern __shared__ __align__(128) char smem[];

    const int z = blockIdx.z;
    const __half* __restrict__ A    = gb.A[z];
    const __half* __restrict__ Bt   = gb.B[z];
    const float*  __restrict__ bias = gb.bias[z];
    float*        __restrict__ C    = gb.C[z];
    __half*       __restrict__ Ch   = gb.Ch[z];
    const bool trv = (OUTH != 0) && (z == gb.trv_z);

    const int tid  = threadIdx.x;
    const int lane = tid & 31;
    const int warp = tid >> 5;
    const int wm   = (warp >> 2) * 64;
    const int wn   = (warp & 3) * 32;
    const int crow = blockIdx.y * 128;
    const int ccol = blockIdx.x * 128;

    const __half* Ap = A  + (size_t)crow * K;
    const __half* Bp = Bt + (size_t)ccol * K;

    const uint32_t smem_base = (uint32_t)__cvta_generic_to_shared(smem);

    const int l_row = tid >> 2;
    const int l_c16 = tid & 3;

    const uint32_t arow_off = (uint32_t)((lane & 7) * ROWB
                            + ((lane >> 3) & 1) * 8 * ROWB + (lane >> 4) * 16);
    const uint32_t brow_off = (uint32_t)((lane & 7) * ROWB
                            + ((lane >> 3) & 1) * 16 + (lane >> 4) * 8 * ROWB);

    auto load_stage = [&](int st, int k0) {
        const uint32_t as = smem_base + st * STAGE_BYTES;
        const uint32_t bs = smem_base + (3 + st) * STAGE_BYTES;
        #pragma unroll
        for (int i = 0; i < 2; i++) {
            const int row = l_row + i * 64;
            const uint32_t so = (uint32_t)(row * ROWB + l_c16 * 16);
            const size_t go = (size_t)row * K + k0 + l_c16 * 8;
            cp_async16(as + so, Ap + go);
            cp_async16(bs + so, Bp + go);
        }
        asm volatile("cp.async.commit_group;\n" ::: "memory");
    };

    float acc[4][4][4];
    #pragma unroll
    for (int mi = 0; mi < 4; mi++)
        #pragma unroll
        for (int ni = 0; ni < 4; ni++)
            #pragma unroll
            for (int r = 0; r < 4; r++) acc[mi][ni][r] = 0.f;

    const int fr = lane >> 2;
    const int fc = lane & 3;

    const int NIT = K / HBK;
    load_stage(0, 0);
    load_stage(1, HBK);

    for (int it = 0; it < NIT; it++) {
        const int cur = it % 3;
        if (it + 1 < NIT) {
            asm volatile("cp.async.wait_group 1;\n" ::: "memory");
        } else {
            asm volatile("cp.async.wait_group 0;\n" ::: "memory");
        }
        __syncthreads();
        if (it + 2 < NIT) load_stage((it + 2) % 3, (it + 2) * HBK);

        const uint32_t as = smem_base + cur * STAGE_BYTES;
        const uint32_t bs = smem_base + (3 + cur) * STAGE_BYTES;

        #pragma unroll
        for (int ks = 0; ks < 2; ks++) {
            const int kb = ks * 32;
            uint32_t af[4][4];
            uint32_t bf[4][2];
            #pragma unroll
            for (int mi = 0; mi < 4; mi++)
                ldm_x4(af[mi][0], af[mi][1], af[mi][2], af[mi][3],
                       as + (wm + mi * 16) * ROWB + kb + arow_off);
            #pragma unroll
            for (int n2 = 0; n2 < 2; n2++)
                ldm_x4(bf[2 * n2][0], bf[2 * n2][1], bf[2 * n2 + 1][0], bf[2 * n2 + 1][1],
                       bs + (wn + n2 * 16) * ROWB + kb + brow_off);
            #pragma unroll
            for (int mi = 0; mi < 4; mi++)
                #pragma unroll
                for (int ni = 0; ni < 4; ni++)
                    mma_f16(acc[mi][ni], af[mi][0], af[mi][1], af[mi][2], af[mi][3],
                            bf[ni][0], bf[ni][1]);
        }
        __syncthreads();
    }

    __half* smt = reinterpret_cast<__half*>(smem);   // transpose staging (trv)

    #pragma unroll
    for (int mi = 0; mi < 4; mi++) {
        #pragma unroll
        for (int ni = 0; ni < 4; ni++) {
            const int row = crow + wm + mi * 16 + fr;
            const int col = ccol + wn + ni * 8 + 2 * fc;
            const float b0 = bias[col], b1 = bias[col + 1];
            float2 v0 = make_float2(acc[mi][ni][0] + b0, acc[mi][ni][1] + b1);
            float2 v1 = make_float2(acc[mi][ni][2] + b0, acc[mi][ni][3] + b1);
            if (RELU) {
                v0.x = fmaxf(v0.x, 0.f); v0.y = fmaxf(v0.y, 0.f);
                v1.x = fmaxf(v1.x, 0.f); v1.y = fmaxf(v1.y, 0.f);
            }
            if (OUTH) {
                if (trv) {
                    const int rl = wm + mi * 16 + fr;       // local row (token)
                    const int cl = wn + ni * 8 + 2 * fc;    // local col (dh)
                    smt[cl * TPH + rl]           = __float2half_rn(v0.x);
                    smt[(cl + 1) * TPH + rl]     = __float2half_rn(v0.y);
                    smt[cl * TPH + rl + 8]       = __float2half_rn(v1.x);
                    smt[(cl + 1) * TPH + rl + 8] = __float2half_rn(v1.y);
                } else {
                    *reinterpret_cast<__half2*>(Ch + (size_t)row * N + col) =
                        __floats2half2_rn(v0.x, v0.y);
                    *reinterpret_cast<__half2*>(Ch + (size_t)(row + 8) * N + col) =
                        __floats2half2_rn(v1.x, v1.y);
                }
            } else {
                *reinterpret_cast<float2*>(C + (size_t)row * N + col)       = v0;
                *reinterpret_cast<float2*>(C + (size_t)(row + 8) * N + col) = v1;
            }
        }
    }

    if (trv) {
        __syncthreads();   // transpose tile fully staged
        const int bb   = crow >> 10;         // batch (tiles never cross batch)
        const int tok0 = crow & 1023;
        const int cl   = tid >> 1;           // 0..127 (dh col within tile)
        const int seg  = tid & 1;            // 64-half segment
        __half* dstp = Ch + ((size_t)bb * DMODEL + ccol + cl) * SEQ + tok0 + seg * 64;
        const __half* srcp = smt + cl * TPH + seg * 64;
        #pragma unroll
        for (int i = 0; i < 8; i++)
            reinterpret_cast<uint4*>(dstp)[i] =
                reinterpret_cast<const uint4*>(srcp)[i];
    }
}

// ---------------------------------------------------------------------------
// f16 flash attention (R13-proven). 256 threads, q tile 128, kv tile 64.
// R7 pipeline; softmax: f16x2 exp2 (ex2.approx.f16x2) + ones-mma row sums.
// ---------------------------------------------------------------------------
#define FPB 144
#define FKV_B (64 * FPB)
#define FQ_B  (128 * FPB)
#define FLASH_SMEM (FQ_B + 4 * FKV_B)

__global__ void __launch_bounds__(256)
flash_f16(const __half* __restrict__ Qp, const __half* __restrict__ Kp,
          const __half* __restrict__ Vt, __half* __restrict__ O)
{
    extern __shared__ __align__(128) char fsm[];
    const uint32_t qsb = (uint32_t)__cvta_generic_to_shared(fsm);
    const uint32_t ksb = qsb + FQ_B;
    const uint32_t vsb = qsb + FQ_B + 2 * FKV_B;

    const int tid  = threadIdx.x;
    const int lane = tid & 31;
    const int w    = tid >> 5;
    const int fr   = lane >> 2;
    const int fc   = lane & 3;

    const int qt = blockIdx.x;
    const int b  = blockIdx.y >> 4;
    const int h  = blockIdx.y & 15;

    const size_t qoff = ((size_t)b * SEQ + qt * 128) * DMODEL + h * DHEAD;
    const size_t koff = (size_t)b * SEQ * DMODEL + h * DHEAD;
    const size_t voff = ((size_t)b * DMODEL + h * DHEAD) * SEQ;

    const uint32_t arow_off = (uint32_t)((lane & 7) * FPB
                            + ((lane >> 3) & 1) * 8 * FPB + (lane >> 4) * 16);
    const uint32_t brow_off = (uint32_t)((lane & 7) * FPB
                            + ((lane >> 3) & 1) * 16 + (lane >> 4) * 8 * FPB);

    #pragma unroll
    for (int j = 0; j < 4; j++) {
        const int idx = tid + j * 256;
        const int row = idx >> 3, ch = idx & 7;
        cp_async16(qsb + row * FPB + ch * 16, Qp + qoff + (size_t)row * DMODEL + ch * 8);
    }
    auto stage_kv = [&](int buf, int kt) {
        #pragma unroll
        for (int j = 0; j < 2; j++) {
            const int idx = tid + j * 256;
            const int row = idx >> 3, ch = idx & 7;
            cp_async16(ksb + buf * FKV_B + row * FPB + ch * 16,
                       Kp + koff + (size_t)(kt * 64 + row) * DMODEL + ch * 8);
            cp_async16(vsb + buf * FKV_B + row * FPB + ch * 16,
                       Vt + voff + (size_t)row * SEQ + kt * 64 + ch * 8);
        }
        asm volatile("cp.async.commit_group;\n" ::: "memory");
    };
    stage_kv(0, 0);   // commits q copies too

    float m0 = -1e30f, m1 = -1e30f;
    float oacc[8][4];
    float lacc[4];    // persistent row-sum accumulator (ones-mma output)
    #pragma unroll
    for (int ni = 0; ni < 8; ni++)
        #pragma unroll
        for (int r = 0; r < 4; r++) oacc[ni][r] = 0.f;
    #pragma unroll
    for (int r = 0; r < 4; r++) lacc[r] = 0.f;

    const int qrow = w * 16;
    const int NT = SEQ / 64;

    for (int kt = 0; kt < NT; kt++) {
        const int cur = kt & 1;
        if (kt + 1 < NT) {
            stage_kv(cur ^ 1, kt + 1);
            asm volatile("cp.async.wait_group 1;\n" ::: "memory");
        } else {
            asm volatile("cp.async.wait_group 0;\n" ::: "memory");
        }
        __syncthreads();

        const uint32_t kb_s = ksb + cur * FKV_B;
        const uint32_t vb_s = vsb + cur * FKV_B;

        // ---- S = Q K^T ----
        float sacc[8][4];
        #pragma unroll
        for (int ni = 0; ni < 8; ni++)
            #pragma unroll
            for (int r = 0; r < 4; r++) sacc[ni][r] = 0.f;

        #pragma unroll
        for (int kg = 0; kg < 4; kg++) {
            const int kb = kg * 32;
            uint32_t a0, a1, a2, a3;
            ldm_x4(a0, a1, a2, a3, qsb + qrow * FPB + kb + arow_off);
            uint32_t bf[8][2];
            #pragma unroll
            for (int n2 = 0; n2 < 4; n2++)
                ldm_x4(bf[2 * n2][0], bf[2 * n2][1], bf[2 * n2 + 1][0], bf[2 * n2 + 1][1],
                       kb_s + (n2 * 16) * FPB + kb + brow_off);
            #pragma unroll
            for (int ni = 0; ni < 8; ni++)
                mma_f16(sacc[ni], a0, a1, a2, a3, bf[ni][0], bf[ni][1]);
        }

        // ---- online softmax: max, corr, f16x2 exp2 ----
        float mx0 = -1e30f, mx1 = -1e30f;
        #pragma unroll
        for (int ni = 0; ni < 8; ni++) {
            sacc[ni][0] *= SCALE_L2E; sacc[ni][1] *= SCALE_L2E;
            sacc[ni][2] *= SCALE_L2E; sacc[ni][3] *= SCALE_L2E;
            mx0 = fmaxf(mx0, fmaxf(sacc[ni][0], sacc[ni][1]));
            mx1 = fmaxf(mx1, fmaxf(sacc[ni][2], sacc[ni][3]));
        }
        mx0 = fmaxf(mx0, __shfl_xor_sync(0xffffffffu, mx0, 1));
        mx0 = fmaxf(mx0, __shfl_xor_sync(0xffffffffu, mx0, 2));
        mx1 = fmaxf(mx1, __shfl_xor_sync(0xffffffffu, mx1, 1));
        mx1 = fmaxf(mx1, __shfl_xor_sync(0xffffffffu, mx1, 2));

        const float mn0 = fmaxf(m0, mx0), mn1 = fmaxf(m1, mx1);
        const float corr0 = exp2f(m0 - mn0), corr1 = exp2f(m1 - mn1);
        m0 = mn0; m1 = mn1;

        // P fragments directly via f16x2 exp2
        uint32_t pf[8][2];
        #pragma unroll
        for (int ni = 0; ni < 8; ni++) {
            pf[ni][0] = exp2_h2(sacc[ni][0] - mn0, sacc[ni][1] - mn0);
            pf[ni][1] = exp2_h2(sacc[ni][2] - mn1, sacc[ni][3] - mn1);
        }

        // rescale running accumulators
        #pragma unroll
        for (int ni = 0; ni < 8; ni++) {
            oacc[ni][0] *= corr0; oacc[ni][1] *= corr0;
            oacc[ni][2] *= corr1; oacc[ni][3] *= corr1;
        }
        lacc[0] *= corr0; lacc[1] *= corr0;
        lacc[2] *= corr1; lacc[3] *= corr1;

        // ---- O += P V  and  l += P @ ones ----
        #pragma unroll
        for (int kg = 0; kg < 4; kg++) {
            const int kb = kg * 32;
            const uint32_t a0 = pf[2 * kg][0];
            const uint32_t a1 = pf[2 * kg][1];
            const uint32_t a2 = pf[2 * kg + 1][0];
            const uint32_t a3 = pf[2 * kg + 1][1];
            uint32_t bf[8][2];
            #pragma unroll
            for (int n2 = 0; n2 < 4; n2++)
                ldm_x4(bf[2 * n2][0], bf[2 * n2][1], bf[2 * n2 + 1][0], bf[2 * n2 + 1][1],
                       vb_s + (n2 * 16) * FPB + kb + brow_off);
            #pragma unroll
            for (int ni = 0; ni < 8; ni++)
                mma_f16(oacc[ni], a0, a1, a2, a3, bf[ni][0], bf[ni][1]);
            mma_f16(lacc, a0, a1, a2, a3, ONES_H2, ONES_H2);   // row sums
        }
        __syncthreads();   // all reads of cur done before refill next iter
    }

    const float inv0 = 1.f / lacc[0];
    const float inv1 = 1.f / lacc[2];
    const size_t row0 = (size_t)b * SEQ + qt * 128 + qrow + fr;
    const size_t row1 = row0 + 8;
    #pragma unroll
    for (int ni = 0; ni < 8; ni++) {
        const int col = h * DHEAD + ni * 8 + 2 * fc;
        *reinterpret_cast<__half2*>(O + row0 * DMODEL + col) =
            __floats2half2_rn(oacc[ni][0] * inv0, oacc[ni][1] * inv0);
        *reinterpret_cast<__half2*>(O + row1 * DMODEL + col) =
            __floats2half2_rn(oacc[ni][2] * inv1, oacc[ni][3] * inv1);
    }
}

// ---------------------------------------------------------------------------
// Fused residual add + LayerNorm (float4 vectorized)
// ---------------------------------------------------------------------------
template<int WH>
__global__ void __launch_bounds__(256)
add_ln(const float* __restrict__ A, const float* __restrict__ R,
       const float* __restrict__ g, const float* __restrict__ be,
       float* __restrict__ out, __half* __restrict__ outh)
{
    const int row = blockIdx.x;
    const int tid = threadIdx.x;
    const size_t base = (size_t)row * DMODEL;
    const int c = tid * 4;

    float4 a4 = *reinterpret_cast<const float4*>(A + base + c);
    float4 r4 = *reinterpret_cast<const float4*>(R + base + c);
    float x[4] = {a4.x + r4.x, a4.y + r4.y, a4.z + r4.z, a4.w + r4.w};
    float sum = x[0] + x[1] + x[2] + x[3];

    __shared__ float red[8];
    __shared__ float red2[8];
    #pragma unroll
    for (int off = 16; off; off >>= 1)
        sum += __shfl_xor_sync(0xffffffffu, sum, off);
    if ((tid & 31) == 0) red[tid >> 5] = sum;
    __syncthreads();
    float tot = 0.f;
    #pragma unroll
    for (int wq = 0; wq < 8; wq++) tot += red[wq];
    const float mean = tot * (1.f / (float)DMODEL);

    float vsum = 0.f;
    #pragma unroll
    for (int i = 0; i < 4; i++) {
        x[i] -= mean;
        vsum += x[i] * x[i];
    }
    #pragma unroll
    for (int off = 16; off; off >>= 1)
        vsum += __shfl_xor_sync(0xffffffffu, vsum, off);
    if ((tid & 31) == 0) red2[tid >> 5] = vsum;
    __syncthreads();
    float vtot = 0.f;
    #pragma unroll
    for (int wq = 0; wq < 8; wq++) vtot += red2[wq];
    const float rstd = rsqrtf(vtot * (1.f / (float)DMODEL) + LN_EPS);

    float4 g4  = *reinterpret_cast<const float4*>(g + c);
    float4 be4 = *reinterpret_cast<const float4*>(be + c);
    float4 v;
    v.x = x[0] * rstd * g4.x + be4.x;
    v.y = x[1] * rstd * g4.y + be4.y;
    v.z = x[2] * rstd * g4.z + be4.z;
    v.w = x[3] * rstd * g4.w + be4.w;
    *reinterpret_cast<float4*>(out + base + c) = v;
    if (WH) {
        *reinterpret_cast<__half2*>(outh + base + c)     = __floats2half2_rn(v.x, v.y);
        *reinterpret_cast<__half2*>(outh + base + c + 2) = __floats2half2_rn(v.z, v.w);
    }
}

// ---------------------------------------------------------------------------
// Launch
// ---------------------------------------------------------------------------
extern "C" void kernel_launch(void* const* d_in, const int* in_sizes, int n_in,
                              void* d_out, int out_size)
{
    (void)in_sizes; (void)n_in; (void)out_size;

    const float* Q   = (const float*)d_in[0];
    const float* Kin = (const float*)d_in[1];
    const float* Wq  = (const float*)d_in[2];
    const float* bq  = (const float*)d_in[3];
    const float* Wk  = (const float*)d_in[4];
    const float* bk  = (const float*)d_in[5];
    const float* Wv  = (const float*)d_in[6];
    const float* bv  = (const float*)d_in[7];
    const float* Wo  = (const float*)d_in[8];
    const float* bo  = (const float*)d_in[9];
    const float* W1  = (const float*)d_in[10];
    const float* b1  = (const float*)d_in[11];
    const float* W2  = (const float*)d_in[12];
    const float* b2  = (const float*)d_in[13];
    const float* g0  = (const float*)d_in[14];
    const float* be0 = (const float*)d_in[15];
    const float* g1  = (const float*)d_in[16];
    const float* be1 = (const float*)d_in[17];
    float* out = (float*)d_out;

    float  *po, *px, *py;
    __half *qih, *kih, *pqh, *pkh, *pvt, *patth, *pxh, *pffh, *pw;
    cudaGetSymbolAddress((void**)&po,    g_o);
    cudaGetSymbolAddress((void**)&px,    g_x);
    cudaGetSymbolAddress((void**)&py,    g_y);
    cudaGetSymbolAddress((void**)&qih,   h_qi);
    cudaGetSymbolAddress((void**)&kih,   h_ki);
    cudaGetSymbolAddress((void**)&pqh,   h_q);
    cudaGetSymbolAddress((void**)&pkh,   h_k);
    cudaGetSymbolAddress((void**)&pvt,   h_vt);
    cudaGetSymbolAddress((void**)&patth, h_att);
    cudaGetSymbolAddress((void**)&pxh,   h_x);
    cudaGetSymbolAddress((void**)&pffh,  h_ff);
    cudaGetSymbolAddress((void**)&pw,    h_w);

    __half* wtq = pw;
    __half* wtk = pw + 1 * 1024 * 1024;
    __half* wtv = pw + 2 * 1024 * 1024;
    __half* wto = pw + 3 * 1024 * 1024;
    __half* wt1 = pw + 4 * 1024 * 1024;
    __half* wt2 = pw + 8 * 1024 * 1024;

    cudaFuncSetAttribute(gemm_f16<0, 0>, cudaFuncAttributeMaxDynamicSharedMemorySize, GEMM_SMEM);
    cudaFuncSetAttribute(gemm_f16<0, 1>, cudaFuncAttributeMaxDynamicSharedMemorySize, GEMM_SMEM);
    cudaFuncSetAttribute(gemm_f16<1, 1>, cudaFuncAttributeMaxDynamicSharedMemorySize, GEMM_SMEM);
    cudaFuncSetAttribute(flash_f16, cudaFuncAttributeMaxDynamicSharedMemorySize, FLASH_SMEM);

    // pre-passes
    conv_w<<<dim3(32, 32),  256>>>(Wq, wtq, 1024, 1024);
    conv_w<<<dim3(32, 32),  256>>>(Wk, wtk, 1024, 1024);
    conv_w<<<dim3(32, 32),  256>>>(Wv, wtv, 1024, 1024);
    conv_w<<<dim3(32, 32),  256>>>(Wo, wto, 1024, 1024);
    conv_w<<<dim3(128, 32), 256>>>(W1, wt1, 1024, 4096);
    conv_w<<<dim3(32, 128), 256>>>(W2, wt2, 4096, 1024);
    conv_a<<<ROWS * DMODEL / 1024, 256>>>(Q,   qih);
    conv_a<<<ROWS * DMODEL / 1024, 256>>>(Kin, kih);

    // QKV projections (f16 out); V instance stores TRANSPOSED via smem staging
    {
        GemmBatch gb = {};
        gb.A[0] = qih; gb.B[0] = wtq; gb.bias[0] = bq; gb.Ch[0] = pqh;
        gb.A[1] = kih; gb.B[1] = wtk; gb.bias[1] = bk; gb.Ch[1] = pkh;
        gb.A[2] = kih; gb.B[2] = wtv; gb.bias[2] = bv; gb.Ch[2] = pvt;
        gb.trv_z = 2;
        gemm_f16<0, 1><<<dim3(8, 32, 3), 256, GEMM_SMEM>>>(gb, ROWS, DMODEL, DMODEL);
    }

    // flash attention (V already transposed)
    flash_f16<<<dim3(SEQ / 128, BATCH * NHEAD), 256, FLASH_SMEM>>>(pqh, pkh, pvt, patth);

    // O projection + residual + LN0
    {
        GemmBatch gb = {};
        gb.A[0] = patth; gb.B[0] = wto; gb.bias[0] = bo; gb.C[0] = po;
        gb.trv_z = -1;
        gemm_f16<0, 0><<<dim3(8, 32, 1), 256, GEMM_SMEM>>>(gb, ROWS, DMODEL, DMODEL);
    }
    add_ln<1><<<ROWS, 256>>>(po, Q, g0, be0, px, pxh);

    // FFN
    {
        GemmBatch gb = {};
        gb.A[0] = pxh; gb.B[0] = wt1; gb.bias[0] = b1; gb.Ch[0] = pffh;
        gb.trv_z = -1;
        gemm_f16<1, 1><<<dim3(32, 32, 1), 256, GEMM_SMEM>>>(gb, ROWS, DFF_, DMODEL);
    }
    {
        GemmBatch gb = {};
        gb.A[0] = pffh; gb.B[0] = wt2; gb.bias[0] = b2; gb.C[0] = py;
        gb.trv_z = -1;
        gemm_f16<0, 0><<<dim3(8, 32, 1), 256, GEMM_SMEM>>>(gb, ROWS, DMODEL, DFF_);
    }
    add_ln<0><<<ROWS, 256>>>(py, px, g1, be1, out, nullptr);
}